// round 2
// baseline (speedup 1.0000x reference)
#include <cuda_runtime.h>
#include <math.h>

// Problem constants
#define BATCH 2
#define HEADS 8
#define BHN   16            // BATCH*HEADS
#define LEN   2048
#define DIM   64
#define MRP   1024          // MAX_REL_POS
#define QT128 (LEN/128)     // 16 tiles of 128
#define TRI_TILES (QT128*(QT128+1)/2)   // 136 lower-triangular 128x128 tile pairs
#define OUT_ELEMS ((size_t)BHN*LEN*DIM) // 2,097,152

typedef unsigned long long u64;

// Scratch for R = Q @ embed^T  : [BH][L][MRP]  (128 MB, device-global = legal scratch)
__device__ float g_R[(size_t)BHN * LEN * MRP];

// ---------- packed fp32x2 helpers (2x FFMA throughput on sm_103a) ----------
__device__ __forceinline__ u64 pack2(float lo, float hi) {
    u64 r; asm("mov.b64 %0, {%1, %2};" : "=l"(r) : "f"(lo), "f"(hi)); return r;
}
__device__ __forceinline__ void fma2(u64 &d, u64 a, u64 b) {
    asm("fma.rn.f32x2 %0, %1, %2, %0;" : "+l"(d) : "l"(a), "l"(b));
}
__device__ __forceinline__ float2 unpack2(u64 v) {
    float lo, hi; asm("mov.b64 {%0, %1}, %2;" : "=f"(lo), "=f"(hi) : "l"(v));
    return make_float2(lo, hi);
}

// map linear triangular index t -> (ti, tj), tj <= ti
__device__ __forceinline__ void tri_map(int t, int &ti, int &tj) {
    int i = (int)((sqrtf(8.0f * (float)t + 1.0f) - 1.0f) * 0.5f);
    while ((i + 1) * (i + 2) / 2 <= t) i++;
    while (i * (i + 1) / 2 > t) i--;
    ti = i; tj = t - i * (i + 1) / 2;
}

// ---------------------------------------------------------------------------
// 128x128 GEMM-NT tile body: C(128x128) = A(128x64) * B(128x64)^T
// A,B row-major with row stride DIM(=64). Accumulates into acc[8][4] (f32x2 pairs).
// 256 threads; thread (tx,ty) owns rows ty*8..+7, cols tx*8..+7.
// ---------------------------------------------------------------------------
__device__ __forceinline__ void mm128x128(const float* __restrict__ Ag,
                                          const float* __restrict__ Bg,
                                          u64 acc[8][4]) {
    __shared__ float As[32][132];   // [d][row] transposed
    __shared__ float Bs[32][132];
    const int tid = threadIdx.x;
    const int tx = tid & 15, ty = tid >> 4;
    const int r0 = ty * 8, c0 = tx * 8;
    #pragma unroll
    for (int d0 = 0; d0 < DIM; d0 += 32) {
        #pragma unroll
        for (int i = 0; i < 4; i++) {
            int idx = tid + i * 256;          // 0..1023
            int row = idx >> 3;               // 0..127
            int c4  = (idx & 7) * 4;          // 0..28
            float4 va = *(const float4*)(Ag + (size_t)row * DIM + d0 + c4);
            As[c4+0][row] = va.x; As[c4+1][row] = va.y;
            As[c4+2][row] = va.z; As[c4+3][row] = va.w;
            float4 vb = *(const float4*)(Bg + (size_t)row * DIM + d0 + c4);
            Bs[c4+0][row] = vb.x; Bs[c4+1][row] = vb.y;
            Bs[c4+2][row] = vb.z; Bs[c4+3][row] = vb.w;
        }
        __syncthreads();
        #pragma unroll
        for (int kk = 0; kk < 32; kk++) {
            float4 a0 = *(const float4*)&As[kk][r0];
            float4 a1 = *(const float4*)&As[kk][r0 + 4];
            float4 b0 = *(const float4*)&Bs[kk][c0];
            float4 b1 = *(const float4*)&Bs[kk][c0 + 4];
            u64 bp0 = pack2(b0.x, b0.y), bp1 = pack2(b0.z, b0.w);
            u64 bp2 = pack2(b1.x, b1.y), bp3 = pack2(b1.z, b1.w);
            float av[8] = {a0.x, a0.y, a0.z, a0.w, a1.x, a1.y, a1.z, a1.w};
            #pragma unroll
            for (int i = 0; i < 8; i++) {
                u64 ad = pack2(av[i], av[i]);
                fma2(acc[i][0], ad, bp0);
                fma2(acc[i][1], ad, bp1);
                fma2(acc[i][2], ad, bp2);
                fma2(acc[i][3], ad, bp3);
            }
        }
        __syncthreads();
    }
}

// ---------------- K_zero: clear the attention-output region ----------------
__global__ void k_zero(float* __restrict__ O) {
    size_t i = ((size_t)blockIdx.x * 256 + threadIdx.x) * 4;
    *(float4*)(O + i) = make_float4(0.f, 0.f, 0.f, 0.f);
}

// ---------------- K0: R = Q @ embed^T  ([L x MRP] per bh) -----------------
__global__ void __launch_bounds__(256, 2) k_relgemm(const float* __restrict__ Q,
                                                    const float* __restrict__ E) {
    const int rt = blockIdx.x;          // 0..15 (q tile)
    const int ct = blockIdx.y;          // 0..7  (embed tile)
    const int bh = blockIdx.z;
    const float* Ag = Q + ((size_t)bh * LEN + rt * 128) * DIM;
    const float* Bg = E + (size_t)(ct * 128) * DIM;
    u64 acc[8][4];
    #pragma unroll
    for (int i = 0; i < 8; i++)
        #pragma unroll
        for (int j = 0; j < 4; j++) acc[i][j] = 0ull;
    mm128x128(Ag, Bg, acc);
    const int tx = threadIdx.x & 15, ty = threadIdx.x >> 4;
    float* C = g_R + ((size_t)bh * LEN + rt * 128) * MRP + ct * 128;
    #pragma unroll
    for (int i = 0; i < 8; i++) {
        float* Crow = C + (size_t)(ty * 8 + i) * MRP + tx * 8;
        float2 p0 = unpack2(acc[i][0]), p1 = unpack2(acc[i][1]);
        float2 p2 = unpack2(acc[i][2]), p3 = unpack2(acc[i][3]);
        *(float4*)(Crow)     = make_float4(p0.x, p0.y, p1.x, p1.y);
        *(float4*)(Crow + 4) = make_float4(p2.x, p2.y, p3.x, p3.y);
    }
}

// ---------------- K1: S = Q @ K^T, lower-triangular tiles ------------------
__global__ void __launch_bounds__(256, 2) k_qk(const float* __restrict__ Q,
                                               const float* __restrict__ Kt,
                                               float* __restrict__ Wt) {
    int ti, tj; tri_map(blockIdx.x, ti, tj);
    const int bh = blockIdx.y;
    const float* Ag = Q  + ((size_t)bh * LEN + ti * 128) * DIM;
    const float* Bg = Kt + ((size_t)bh * LEN + tj * 128) * DIM;
    u64 acc[8][4];
    #pragma unroll
    for (int i = 0; i < 8; i++)
        #pragma unroll
        for (int j = 0; j < 4; j++) acc[i][j] = 0ull;
    mm128x128(Ag, Bg, acc);
    const int tx = threadIdx.x & 15, ty = threadIdx.x >> 4;
    float* C = Wt + ((size_t)bh * LEN + ti * 128) * LEN + tj * 128;
    #pragma unroll
    for (int i = 0; i < 8; i++) {
        float* Crow = C + (size_t)(ty * 8 + i) * LEN + tx * 8;
        float2 p0 = unpack2(acc[i][0]), p1 = unpack2(acc[i][1]);
        float2 p2 = unpack2(acc[i][2]), p3 = unpack2(acc[i][3]);
        *(float4*)(Crow)     = make_float4(p0.x, p0.y, p1.x, p1.y);
        *(float4*)(Crow + 4) = make_float4(p2.x, p2.y, p3.x, p3.y);
    }
}

// ---------------- K2: row softmax with folded relative-gather --------------
// logits[q,j] = S[q,j] + R[q, j-q+1023] (if j-q+1023 >= 0), j <= q; else masked.
__global__ void k_softmax(float* __restrict__ Wt) {
    const int q  = blockIdx.x & (LEN - 1);
    const int bh = blockIdx.x >> 11;
    float* Wrow = Wt + ((size_t)bh * LEN + q) * LEN;
    const float* Rrow = g_R + ((size_t)bh * LEN + q) * MRP;
    const int tid = threadIdx.x;

    float val[8];
    float m = -3.0e38f;
    #pragma unroll
    for (int i = 0; i < 8; i++) {
        int j = tid + (i << 8);
        float s = -3.0e38f;
        if (j <= q) {
            s = Wrow[j];
            int e = j - q + (MRP - 1);
            if (e >= 0) s += Rrow[e];
        }
        val[i] = s;
        m = fmaxf(m, s);
    }
    __shared__ float red[33];
    #pragma unroll
    for (int o = 16; o > 0; o >>= 1) m = fmaxf(m, __shfl_xor_sync(0xffffffffu, m, o));
    if ((tid & 31) == 0) red[tid >> 5] = m;
    __syncthreads();
    if (tid < 32) {
        float x = (tid < 8) ? red[tid] : -3.0e38f;
        #pragma unroll
        for (int o = 4; o > 0; o >>= 1) x = fmaxf(x, __shfl_xor_sync(0xffffffffu, x, o));
        if (tid == 0) red[32] = x;
    }
    __syncthreads();
    const float bm = red[32];

    float p[8];
    float sum = 0.f;
    #pragma unroll
    for (int i = 0; i < 8; i++) {
        int j = tid + (i << 8);
        float e = (j <= q) ? __expf(val[i] - bm) : 0.f;
        p[i] = e;
        sum += e;
    }
    #pragma unroll
    for (int o = 16; o > 0; o >>= 1) sum += __shfl_xor_sync(0xffffffffu, sum, o);
    if ((tid & 31) == 0) red[tid >> 5] = sum;
    __syncthreads();
    if (tid < 32) {
        float x = (tid < 8) ? red[tid] : 0.f;
        #pragma unroll
        for (int o = 4; o > 0; o >>= 1) x += __shfl_xor_sync(0xffffffffu, x, o);
        if (tid == 0) red[32] = x;
    }
    __syncthreads();
    const float inv = 1.0f / red[32];
    #pragma unroll
    for (int i = 0; i < 8; i++)
        Wrow[tid + (i << 8)] = p[i] * inv;
}

// ---------------- K3: O = W @ V  (split-K over triangular j-chunks) --------
// Each block: 128 q-rows (tile ti) x 64 dims, over 128 j's (chunk tj), RED epilogue.
__global__ void __launch_bounds__(256, 2) k_pv(const float* __restrict__ Wt,
                                               const float* __restrict__ V,
                                               float* __restrict__ O) {
    int ti, tj; tri_map(blockIdx.x, ti, tj);
    const int bh = blockIdx.y;
    const float* Wg = Wt + ((size_t)bh * LEN + ti * 128) * LEN + tj * 128; // 128x128
    const float* Vg = V  + ((size_t)bh * LEN + tj * 128) * DIM;           // 128x64

    __shared__ float Ws[32][132];   // [j][row] transposed
    __shared__ float Vs[32][68];    // [j][d]
    const int tid = threadIdx.x;
    const int tx = tid & 15, ty = tid >> 4;
    const int r0 = ty * 8, c0 = tx * 4;
    u64 acc[8][2];
    #pragma unroll
    for (int i = 0; i < 8; i++) { acc[i][0] = 0ull; acc[i][1] = 0ull; }

    #pragma unroll
    for (int j0 = 0; j0 < 128; j0 += 32) {
        #pragma unroll
        for (int i = 0; i < 4; i++) {
            int idx = tid + i * 256;
            int row = idx >> 3;
            int c4  = (idx & 7) * 4;
            float4 v = *(const float4*)(Wg + (size_t)row * LEN + j0 + c4);
            Ws[c4+0][row] = v.x; Ws[c4+1][row] = v.y;
            Ws[c4+2][row] = v.z; Ws[c4+3][row] = v.w;
        }
        #pragma unroll
        for (int i = 0; i < 2; i++) {
            int idx = tid + i * 256;
            int jr  = idx >> 4;
            int c4  = (idx & 15) * 4;
            *(float4*)&Vs[jr][c4] = *(const float4*)(Vg + (size_t)(j0 + jr) * DIM + c4);
        }
        __syncthreads();
        #pragma unroll
        for (int kk = 0; kk < 32; kk++) {
            float4 a0 = *(const float4*)&Ws[kk][r0];
            float4 a1 = *(const float4*)&Ws[kk][r0 + 4];
            float4 b  = *(const float4*)&Vs[kk][c0];
            u64 bp0 = pack2(b.x, b.y), bp1 = pack2(b.z, b.w);
            float av[8] = {a0.x, a0.y, a0.z, a0.w, a1.x, a1.y, a1.z, a1.w};
            #pragma unroll
            for (int i = 0; i < 8; i++) {
                u64 ad = pack2(av[i], av[i]);
                fma2(acc[i][0], ad, bp0);
                fma2(acc[i][1], ad, bp1);
            }
        }
        __syncthreads();
    }

    float* Ob = O + ((size_t)bh * LEN + ti * 128) * DIM + c0;
    #pragma unroll
    for (int i = 0; i < 8; i++) {
        float2 p0 = unpack2(acc[i][0]);
        float2 p1 = unpack2(acc[i][1]);
        float* row = Ob + (size_t)(r0 + i) * DIM;
        atomicAdd(row + 0, p0.x);
        atomicAdd(row + 1, p0.y);
        atomicAdd(row + 2, p1.x);
        atomicAdd(row + 3, p1.y);
    }
}

// ---------------------------------------------------------------------------
extern "C" void kernel_launch(void* const* d_in, const int* in_sizes, int n_in,
                              void* d_out, int out_size) {
    const float* q   = (const float*)d_in[0];
    const float* k   = (const float*)d_in[1];
    const float* v   = (const float*)d_in[2];
    const float* rel = (const float*)d_in[3];
    // d_in[4] is the causal mask; causality is applied analytically.

    float* out = (float*)d_out;                 // [BH, L, D]
    float* Wt  = out + OUT_ELEMS;               // [BH, L, L] weights (also logits scratch)

    // 1) zero the attention-output region (PV accumulates with RED)
    k_zero<<<(unsigned)(OUT_ELEMS / 1024), 256>>>(out);

    // 2) R = Q @ embed^T
    dim3 g0(QT128, MRP / 128, BHN);
    k_relgemm<<<g0, 256>>>(q, rel);

    // 3) S = Q @ K^T (lower-triangular tiles) into the weights region
    dim3 g1(TRI_TILES, BHN);
    k_qk<<<g1, 256>>>(q, k, Wt);

    // 4) softmax rows (folds the relative-position gather, writes zeros above diag)
    k_softmax<<<BHN * LEN, 256>>>(Wt);

    // 5) O = W @ V (triangular split-K, atomic accumulate)
    k_pv<<<g1, 256>>>(Wt, v, out);
}

// round 5
// speedup vs baseline: 1.2266x; 1.2266x over previous
#include <cuda_runtime.h>
#include <math.h>

#define BHN   16
#define LEN   2048
#define DIM   64
#define MRP   1024
#define QT    16
#define TRI   136                       // lower-tri 128x128 tiles
#define PVB   72                        // PV blocks per bh (j-chunk 256)
#define OUT_ELEMS ((size_t)BHN*LEN*DIM)

typedef unsigned long long u64;

// scratch: R = Q @ embed^T  [BH][L][MRP]
__device__ float g_R[(size_t)BHN * LEN * MRP];

// smem layout for the NT GEMM kernels (dynamic)
#define AD_STRIDE 258                   // dup-A row stride (2*128 + 2)
#define BS_STRIDE 132
#define SMEM_FLOATS (DIM*AD_STRIDE + DIM*BS_STRIDE)
#define SMEM_BYTES  (SMEM_FLOATS * 4)   // 99840

__device__ __forceinline__ u64 pack2(float lo, float hi) {
    u64 r; asm("mov.b64 %0, {%1, %2};" : "=l"(r) : "f"(lo), "f"(hi)); return r;
}
__device__ __forceinline__ void fma2(u64 &d, u64 a, u64 b) {
    asm("fma.rn.f32x2 %0, %1, %2, %0;" : "+l"(d) : "l"(a), "l"(b));
}
__device__ __forceinline__ float2 unpack2(u64 v) {
    float lo, hi; asm("mov.b64 {%0, %1}, %2;" : "=f"(lo), "=f"(hi) : "l"(v));
    return make_float2(lo, hi);
}

__device__ __forceinline__ void tri_map(int t, int &ti, int &tj) {
    int i = (int)((sqrtf(8.0f * (float)t + 1.0f) - 1.0f) * 0.5f);
    while ((i + 1) * (i + 2) / 2 <= t) i++;
    while (i * (i + 1) / 2 > t) i--;
    ti = i; tj = t - i * (i + 1) / 2;
}

// ---------------------------------------------------------------------------
// C(128x128) = A(128x64) * B(128x64)^T ; A duplicated in smem for LDS.64
// broadcast pairs, B transposed. Single K stage (K=64), one sync.
// ---------------------------------------------------------------------------
__device__ __forceinline__ void mmNT_body(const float* __restrict__ Ag,
                                          const float* __restrict__ Bg,
                                          u64 acc[8][4], float* sm) {
    float* Ad = sm;                         // [64][AD_STRIDE], value at 2r and 2r+1
    float* Bs = sm + DIM * AD_STRIDE;       // [64][BS_STRIDE] transposed
    const int tid = threadIdx.x;
    #pragma unroll
    for (int i = 0; i < 8; i++) {
        int idx = tid + i * 256;            // 0..2047
        int row = idx >> 4;                 // 0..127
        int c4  = (idx & 15) * 4;           // 0..60
        float4 va = *(const float4*)(Ag + (size_t)row * DIM + c4);
        *(float2*)&Ad[(c4+0)*AD_STRIDE + 2*row] = make_float2(va.x, va.x);
        *(float2*)&Ad[(c4+1)*AD_STRIDE + 2*row] = make_float2(va.y, va.y);
        *(float2*)&Ad[(c4+2)*AD_STRIDE + 2*row] = make_float2(va.z, va.z);
        *(float2*)&Ad[(c4+3)*AD_STRIDE + 2*row] = make_float2(va.w, va.w);
        float4 vb = *(const float4*)(Bg + (size_t)row * DIM + c4);
        Bs[(c4+0)*BS_STRIDE + row] = vb.x;
        Bs[(c4+1)*BS_STRIDE + row] = vb.y;
        Bs[(c4+2)*BS_STRIDE + row] = vb.z;
        Bs[(c4+3)*BS_STRIDE + row] = vb.w;
    }
    __syncthreads();
    const int tx = tid & 15, ty = tid >> 4;
    const int r2 = ty * 16;                 // 2*r0
    const int c0 = tx * 8;
    #pragma unroll 8
    for (int kk = 0; kk < DIM; kk++) {
        const float* ad = &Ad[kk * AD_STRIDE + r2];
        const float* bs = &Bs[kk * BS_STRIDE + c0];
        float4 b0 = *(const float4*)(bs);
        float4 b1 = *(const float4*)(bs + 4);
        u64 bp0 = pack2(b0.x, b0.y), bp1 = pack2(b0.z, b0.w);
        u64 bp2 = pack2(b1.x, b1.y), bp3 = pack2(b1.z, b1.w);
        #pragma unroll
        for (int i = 0; i < 8; i++) {
            u64 a = *(const u64*)(ad + 2 * i);
            fma2(acc[i][0], a, bp0);
            fma2(acc[i][1], a, bp1);
            fma2(acc[i][2], a, bp2);
            fma2(acc[i][3], a, bp3);
        }
    }
}

// ---------------- zero the attention-output region -------------------------
__global__ void k_zero(float* __restrict__ O) {
    size_t i = ((size_t)blockIdx.x * 256 + threadIdx.x) * 4;
    *(float4*)(O + i) = make_float4(0.f, 0.f, 0.f, 0.f);
}

// ---------------- R = Q @ embed^T ------------------------------------------
__global__ void __launch_bounds__(256, 2) k_relgemm(const float* __restrict__ Q,
                                                    const float* __restrict__ E) {
    extern __shared__ float sm[];
    const int rt = blockIdx.x, ct = blockIdx.y, bh = blockIdx.z;
    const float* Ag = Q + ((size_t)bh * LEN + rt * 128) * DIM;
    const float* Bg = E + (size_t)(ct * 128) * DIM;
    u64 acc[8][4];
    #pragma unroll
    for (int i = 0; i < 8; i++)
        #pragma unroll
        for (int j = 0; j < 4; j++) acc[i][j] = 0ull;
    mmNT_body(Ag, Bg, acc, sm);
    const int tx = threadIdx.x & 15, ty = threadIdx.x >> 4;
    float* C = g_R + ((size_t)bh * LEN + rt * 128) * MRP + ct * 128;
    #pragma unroll
    for (int i = 0; i < 8; i++) {
        float* Crow = C + (size_t)(ty * 8 + i) * MRP + tx * 8;
        float2 p0 = unpack2(acc[i][0]), p1 = unpack2(acc[i][1]);
        float2 p2 = unpack2(acc[i][2]), p3 = unpack2(acc[i][3]);
        *(float4*)(Crow)     = make_float4(p0.x, p0.y, p1.x, p1.y);
        *(float4*)(Crow + 4) = make_float4(p2.x, p2.y, p3.x, p3.y);
    }
}

// ---------------- S = Q @ K^T + rel (lower-tri tiles) ----------------------
__global__ void __launch_bounds__(256, 2) k_qk(const float* __restrict__ Q,
                                               const float* __restrict__ Kt,
                                               float* __restrict__ Wt) {
    extern __shared__ float sm[];
    int ti, tj; tri_map(blockIdx.x, ti, tj);
    const int bh = blockIdx.y;
    const float* Ag = Q  + ((size_t)bh * LEN + ti * 128) * DIM;
    const float* Bg = Kt + ((size_t)bh * LEN + tj * 128) * DIM;
    u64 acc[8][4];
    #pragma unroll
    for (int i = 0; i < 8; i++)
        #pragma unroll
        for (int j = 0; j < 4; j++) acc[i][j] = 0ull;
    mmNT_body(Ag, Bg, acc, sm);
    const int tx = threadIdx.x & 15, ty = threadIdx.x >> 4;
    const int jb = tj * 128 + tx * 8;
    float* C = Wt + ((size_t)bh * LEN + ti * 128) * LEN + tj * 128;
    #pragma unroll
    for (int i = 0; i < 8; i++) {
        const int qi = ty * 8 + i;
        const int q  = ti * 128 + qi;
        const float* Rrow = g_R + ((size_t)bh * LEN + q) * MRP;
        const int ebase = jb - q + (MRP - 1);
        float r[8];
        #pragma unroll
        for (int cc = 0; cc < 8; cc++) {
            int e = ebase + cc;
            r[cc] = (e >= 0 && e < MRP) ? Rrow[e] : 0.f;
        }
        float2 p0 = unpack2(acc[i][0]), p1 = unpack2(acc[i][1]);
        float2 p2 = unpack2(acc[i][2]), p3 = unpack2(acc[i][3]);
        float* Crow = C + (size_t)qi * LEN + tx * 8;
        *(float4*)(Crow)     = make_float4(p0.x + r[0], p0.y + r[1],
                                           p1.x + r[2], p1.y + r[3]);
        *(float4*)(Crow + 4) = make_float4(p2.x + r[4], p2.y + r[5],
                                           p3.x + r[6], p3.y + r[7]);
    }
}

// ---------------- row softmax (pure streaming, rel already folded) ---------
__global__ void __launch_bounds__(256) k_softmax(float* __restrict__ Wt) {
    const int q  = blockIdx.x & (LEN - 1);
    const int bh = blockIdx.x >> 11;
    float* Wrow = Wt + ((size_t)bh * LEN + q) * LEN;
    const int tid = threadIdx.x;
    const int ja = tid * 4, jb = 1024 + tid * 4;
    float4 wa = *(const float4*)(Wrow + ja);
    float4 wb = *(const float4*)(Wrow + jb);
    float va[4] = {wa.x, wa.y, wa.z, wa.w};
    float vb[4] = {wb.x, wb.y, wb.z, wb.w};

    float m = -3.0e38f;
    #pragma unroll
    for (int c = 0; c < 4; c++) {
        if (ja + c <= q) m = fmaxf(m, va[c]);
        if (jb + c <= q) m = fmaxf(m, vb[c]);
    }
    __shared__ float red[9];
    #pragma unroll
    for (int o = 16; o > 0; o >>= 1) m = fmaxf(m, __shfl_xor_sync(0xffffffffu, m, o));
    if ((tid & 31) == 0) red[tid >> 5] = m;
    __syncthreads();
    if (tid == 0) {
        float x = red[0];
        #pragma unroll
        for (int w = 1; w < 8; w++) x = fmaxf(x, red[w]);
        red[8] = x;
    }
    __syncthreads();
    const float bm = red[8];

    float ea[4], eb[4], s = 0.f;
    #pragma unroll
    for (int c = 0; c < 4; c++) {
        ea[c] = (ja + c <= q) ? __expf(va[c] - bm) : 0.f;
        eb[c] = (jb + c <= q) ? __expf(vb[c] - bm) : 0.f;
        s += ea[c] + eb[c];
    }
    __syncthreads();
    #pragma unroll
    for (int o = 16; o > 0; o >>= 1) s += __shfl_xor_sync(0xffffffffu, s, o);
    if ((tid & 31) == 0) red[tid >> 5] = s;
    __syncthreads();
    if (tid == 0) {
        float x = red[0];
        #pragma unroll
        for (int w = 1; w < 8; w++) x += red[w];
        red[8] = x;
    }
    __syncthreads();
    const float inv = 1.0f / red[8];
    *(float4*)(Wrow + ja) = make_float4(ea[0]*inv, ea[1]*inv, ea[2]*inv, ea[3]*inv);
    *(float4*)(Wrow + jb) = make_float4(eb[0]*inv, eb[1]*inv, eb[2]*inv, eb[3]*inv);
}

// ---------------- O = W @ V  (j-chunk 256 per block, atomic epilogue) ------
__global__ void __launch_bounds__(256) k_pv(const float* __restrict__ Wt,
                                            const float* __restrict__ V,
                                            float* __restrict__ O) {
    int ti = 0, rem = blockIdx.x;
    while (rem >= (ti / 2 + 1)) { rem -= ti / 2 + 1; ti++; }
    const int tjc = rem;
    const int bh = blockIdx.y;

    __shared__ float Wd[32 * 258];          // dup-W [j][2q]
    __shared__ float Vs[32 * 68];           // [j][d]
    const int tid = threadIdx.x;
    const int tx = tid & 7, ty = tid >> 3;  // 8 x 32
    const int r2 = ty * 8;                  // 2*(ty*4)
    const int c0 = tx * 8;
    u64 acc[4][4];
    #pragma unroll
    for (int i = 0; i < 4; i++)
        #pragma unroll
        for (int j = 0; j < 4; j++) acc[i][j] = 0ull;

    for (int sub = 0; sub < 2; sub++) {
        const int tj = tjc * 2 + sub;
        if (tj > ti) break;
        const float* Wg = Wt + ((size_t)bh * LEN + ti * 128) * LEN + tj * 128;
        const float* Vg = V  + ((size_t)bh * LEN + tj * 128) * DIM;
        for (int j0 = 0; j0 < 128; j0 += 32) {
            __syncthreads();
            #pragma unroll
            for (int i = 0; i < 4; i++) {
                int idx = tid + i * 256;
                int qr  = idx >> 3;
                int j4  = (idx & 7) * 4;
                float4 w = *(const float4*)(Wg + (size_t)qr * LEN + j0 + j4);
                *(float2*)&Wd[(j4+0)*258 + 2*qr] = make_float2(w.x, w.x);
                *(float2*)&Wd[(j4+1)*258 + 2*qr] = make_float2(w.y, w.y);
                *(float2*)&Wd[(j4+2)*258 + 2*qr] = make_float2(w.z, w.z);
                *(float2*)&Wd[(j4+3)*258 + 2*qr] = make_float2(w.w, w.w);
            }
            #pragma unroll
            for (int i = 0; i < 2; i++) {
                int idx = tid + i * 256;
                int jr  = idx >> 4;
                int c4  = (idx & 15) * 4;
                *(float4*)&Vs[jr * 68 + c4] =
                    *(const float4*)(Vg + (size_t)(j0 + jr) * DIM + c4);
            }
            __syncthreads();
            #pragma unroll 8
            for (int kk = 0; kk < 32; kk++) {
                const float* wd = &Wd[kk * 258 + r2];
                const float* vs = &Vs[kk * 68 + c0];
                float4 b0 = *(const float4*)(vs);
                float4 b1 = *(const float4*)(vs + 4);
                u64 bp0 = pack2(b0.x, b0.y), bp1 = pack2(b0.z, b0.w);
                u64 bp2 = pack2(b1.x, b1.y), bp3 = pack2(b1.z, b1.w);
                #pragma unroll
                for (int i = 0; i < 4; i++) {
                    u64 a = *(const u64*)(wd + 2 * i);
                    fma2(acc[i][0], a, bp0);
                    fma2(acc[i][1], a, bp1);
                    fma2(acc[i][2], a, bp2);
                    fma2(acc[i][3], a, bp3);
                }
            }
        }
    }

    #pragma unroll
    for (int i = 0; i < 4; i++) {
        float* row = O + ((size_t)bh * LEN + ti * 128 + ty * 4 + i) * DIM + c0;
        float2 p0 = unpack2(acc[i][0]), p1 = unpack2(acc[i][1]);
        float2 p2 = unpack2(acc[i][2]), p3 = unpack2(acc[i][3]);
        atomicAdd(row + 0, p0.x); atomicAdd(row + 1, p0.y);
        atomicAdd(row + 2, p1.x); atomicAdd(row + 3, p1.y);
        atomicAdd(row + 4, p2.x); atomicAdd(row + 5, p2.y);
        atomicAdd(row + 6, p3.x); atomicAdd(row + 7, p3.y);
    }
}

// ---------------------------------------------------------------------------
extern "C" void kernel_launch(void* const* d_in, const int* in_sizes, int n_in,
                              void* d_out, int out_size) {
    const float* q   = (const float*)d_in[0];
    const float* k   = (const float*)d_in[1];
    const float* v   = (const float*)d_in[2];
    const float* rel = (const float*)d_in[3];

    float* out = (float*)d_out;
    float* Wt  = out + OUT_ELEMS;

    cudaFuncSetAttribute(k_relgemm, cudaFuncAttributeMaxDynamicSharedMemorySize, SMEM_BYTES);
    cudaFuncSetAttribute(k_qk,      cudaFuncAttributeMaxDynamicSharedMemorySize, SMEM_BYTES);

    k_zero<<<(unsigned)(OUT_ELEMS / 1024), 256>>>(out);

    dim3 g0(QT, MRP / 128, BHN);
    k_relgemm<<<g0, 256, SMEM_BYTES>>>(q, rel);

    dim3 g1(TRI, BHN);
    k_qk<<<g1, 256, SMEM_BYTES>>>(q, k, Wt);

    k_softmax<<<BHN * LEN, 256>>>(Wt);

    dim3 g2(PVB, BHN);
    k_pv<<<g2, 256>>>(Wt, v, out);
}

// round 8
// speedup vs baseline: 2.0550x; 1.6753x over previous
#include <cuda_runtime.h>
#include <cuda_bf16.h>
#include <math.h>
#include <stdint.h>

#define BHN   16
#define LEN   2048
#define DIM   64
#define MRP   1024
#define QT    16
#define TRI   136
#define OUT_ELEMS ((size_t)BHN*LEN*DIM)

typedef unsigned long long u64;

// scratch: R = Q @ embed^T  [BH][L][MRP]
__device__ float g_R[(size_t)BHN * LEN * MRP];

// ---------------- split fp32 -> (bf16 hi, bf16 lo) packed pairs ------------
__device__ __forceinline__ void split_pair(float x, float y,
                                           uint32_t &h, uint32_t &l) {
    __nv_bfloat16 hx = __float2bfloat16_rn(x), hy = __float2bfloat16_rn(y);
    float rx = x - __bfloat162float(hx), ry = y - __bfloat162float(hy);
    __nv_bfloat16 lx = __float2bfloat16_rn(rx), ly = __float2bfloat16_rn(ry);
    h = (uint32_t)__bfloat16_as_ushort(hx) | ((uint32_t)__bfloat16_as_ushort(hy) << 16);
    l = (uint32_t)__bfloat16_as_ushort(lx) | ((uint32_t)__bfloat16_as_ushort(ly) << 16);
}

// mma.sync m16n8k16 row.col f32.bf16.bf16.f32 (portable, no 'a'-target needed)
__device__ __forceinline__ void mma16816(float d[4], uint32_t a0, uint32_t a1,
                                         uint32_t a2, uint32_t a3,
                                         uint32_t b0, uint32_t b1) {
    asm volatile(
        "mma.sync.aligned.m16n8k16.row.col.f32.bf16.bf16.f32 "
        "{%0,%1,%2,%3}, {%4,%5,%6,%7}, {%8,%9}, {%0,%1,%2,%3};"
        : "+f"(d[0]), "+f"(d[1]), "+f"(d[2]), "+f"(d[3])
        : "r"(a0), "r"(a1), "r"(a2), "r"(a3), "r"(b0), "r"(b1));
}

__device__ __forceinline__ void tri_map(int t, int &ti, int &tj) {
    int i = (int)((sqrtf(8.0f * (float)t + 1.0f) - 1.0f) * 0.5f);
    while ((i + 1) * (i + 2) / 2 <= t) i++;
    while (i * (i + 1) / 2 > t) i--;
    ti = i; tj = t - i * (i + 1) / 2;
}

// smem strides (bf16 elements). 72*2=144B and 136*2=272B -> frag LDS.32 are
// conflict-free: bank = (4g + t) mod 32, distinct for g=0..7, t=0..3.
#define STQ 72
#define STP 136

// qk/relgemm smem map (bf16 units): AH[128][72], AL, BH, BL
#define QK_AH 0
#define QK_AL (128*STQ)
#define QK_BH (2*128*STQ)
#define QK_BL (3*128*STQ)
#define QK_SMEM (4*128*STQ*2)            // 73728 bytes

// pv smem map: WH[128][136], WL, VH[64][136], VL
#define PV_WH 0
#define PV_WL (128*STP)
#define PV_VH (2*128*STP)
#define PV_VL (2*128*STP + 64*STP)
#define PV_SMEM ((2*128*STP + 2*64*STP)*2)  // 104448 bytes

// ---------------- zero the attention-output region -------------------------
__global__ void k_zero(float* __restrict__ O) {
    size_t i = ((size_t)blockIdx.x * 256 + threadIdx.x) * 4;
    *(float4*)(O + i) = make_float4(0.f, 0.f, 0.f, 0.f);
}

// ---------------------------------------------------------------------------
// Shared 128x128 NT tile body: fill split-bf16 smem from A[128x64], B[128x64]
// (row-major, stride DIM) and run the 3-product mma loop into acc[2][8][4].
// 256 threads, warp grid 4x2 (warp tile 32 rows x 64 cols).
// ---------------------------------------------------------------------------
__device__ __forceinline__ void qk_body(const float* __restrict__ Ag,
                                        const float* __restrict__ Bg,
                                        uint16_t* sm, float acc[2][8][4]) {
    const int tid = threadIdx.x;
    uint32_t* AH = (uint32_t*)(sm + QK_AH);
    uint32_t* AL = (uint32_t*)(sm + QK_AL);
    uint32_t* BH = (uint32_t*)(sm + QK_BH);
    uint32_t* BL = (uint32_t*)(sm + QK_BL);
    #pragma unroll
    for (int it = 0; it < 8; it++) {
        int idx = tid + it * 256;        // 2048 float4 slots (128 rows x 16)
        int row = idx >> 4;
        int c4  = (idx & 15) * 4;
        int so  = (row * STQ + c4) >> 1; // u32 index, c4 even
        float4 va = *(const float4*)(Ag + (size_t)row * DIM + c4);
        uint32_t h, l;
        split_pair(va.x, va.y, h, l); AH[so] = h;     AL[so] = l;
        split_pair(va.z, va.w, h, l); AH[so + 1] = h; AL[so + 1] = l;
        float4 vb = *(const float4*)(Bg + (size_t)row * DIM + c4);
        split_pair(vb.x, vb.y, h, l); BH[so] = h;     BL[so] = l;
        split_pair(vb.z, vb.w, h, l); BH[so + 1] = h; BL[so + 1] = l;
    }
    __syncthreads();

    const int w = tid >> 5, lane = tid & 31;
    const int wr = w >> 1, wc = w & 1;
    const int g = lane >> 2, t = lane & 3;
    #pragma unroll
    for (int ks = 0; ks < 4; ks++) {
        const int k0 = ks * 16 + 2 * t;
        uint32_t ah[2][4], al[2][4];
        #pragma unroll
        for (int mi = 0; mi < 2; mi++) {
            int r = wr * 32 + mi * 16 + g;
            int o0 = (r * STQ + k0) >> 1, o1 = ((r + 8) * STQ + k0) >> 1;
            ah[mi][0] = AH[o0];     ah[mi][1] = AH[o1];
            ah[mi][2] = AH[o0 + 4]; ah[mi][3] = AH[o1 + 4];
            al[mi][0] = AL[o0];     al[mi][1] = AL[o1];
            al[mi][2] = AL[o0 + 4]; al[mi][3] = AL[o1 + 4];
        }
        #pragma unroll
        for (int ni = 0; ni < 8; ni++) {
            int n = wc * 64 + ni * 8 + g;
            int ob = (n * STQ + k0) >> 1;
            uint32_t bh0 = BH[ob], bh1 = BH[ob + 4];
            uint32_t bl0 = BL[ob], bl1 = BL[ob + 4];
            #pragma unroll
            for (int mi = 0; mi < 2; mi++) {
                mma16816(acc[mi][ni], ah[mi][0], ah[mi][1], ah[mi][2], ah[mi][3], bh0, bh1);
                mma16816(acc[mi][ni], ah[mi][0], ah[mi][1], ah[mi][2], ah[mi][3], bl0, bl1);
                mma16816(acc[mi][ni], al[mi][0], al[mi][1], al[mi][2], al[mi][3], bh0, bh1);
            }
        }
    }
}

// ---------------- R = Q @ embed^T ------------------------------------------
__global__ void __launch_bounds__(256, 2) k_relgemm(const float* __restrict__ Q,
                                                    const float* __restrict__ E) {
    extern __shared__ uint16_t smq[];
    const int rt = blockIdx.x, ct = blockIdx.y, bh = blockIdx.z;
    float acc[2][8][4];
    #pragma unroll
    for (int a = 0; a < 2; a++)
        #pragma unroll
        for (int b = 0; b < 8; b++)
            #pragma unroll
            for (int c = 0; c < 4; c++) acc[a][b][c] = 0.f;
    qk_body(Q + ((size_t)bh * LEN + rt * 128) * DIM,
            E + (size_t)(ct * 128) * DIM, smq, acc);

    const int tid = threadIdx.x, w = tid >> 5, lane = tid & 31;
    const int wr = w >> 1, wc = w & 1, g = lane >> 2, t = lane & 3;
    #pragma unroll
    for (int mi = 0; mi < 2; mi++) {
        int q0 = rt * 128 + wr * 32 + mi * 16 + g;
        float* R0 = g_R + ((size_t)bh * LEN + q0) * MRP + ct * 128;
        float* R1 = R0 + 8 * MRP;
        #pragma unroll
        for (int ni = 0; ni < 8; ni++) {
            int c = wc * 64 + ni * 8 + 2 * t;
            *(float2*)(R0 + c) = make_float2(acc[mi][ni][0], acc[mi][ni][1]);
            *(float2*)(R1 + c) = make_float2(acc[mi][ni][2], acc[mi][ni][3]);
        }
    }
}

// ---------------- S = Q @ K^T + rel (lower-tri tiles) ----------------------
__global__ void __launch_bounds__(256, 2) k_qk(const float* __restrict__ Q,
                                               const float* __restrict__ Kt,
                                               float* __restrict__ Wt) {
    extern __shared__ uint16_t smq[];
    int ti, tj; tri_map(blockIdx.x, ti, tj);
    const int bh = blockIdx.y;
    float acc[2][8][4];
    #pragma unroll
    for (int a = 0; a < 2; a++)
        #pragma unroll
        for (int b = 0; b < 8; b++)
            #pragma unroll
            for (int c = 0; c < 4; c++) acc[a][b][c] = 0.f;
    qk_body(Q + ((size_t)bh * LEN + ti * 128) * DIM,
            Kt + ((size_t)bh * LEN + tj * 128) * DIM, smq, acc);

    const int tid = threadIdx.x, w = tid >> 5, lane = tid & 31;
    const int wr = w >> 1, wc = w & 1, g = lane >> 2, t = lane & 3;
    #pragma unroll
    for (int mi = 0; mi < 2; mi++) {
        #pragma unroll
        for (int rh = 0; rh < 2; rh++) {
            int q0 = ti * 128 + wr * 32 + mi * 16 + g + rh * 8;
            const float* Rrow = g_R + ((size_t)bh * LEN + q0) * MRP;
            float* Wrow = Wt + ((size_t)bh * LEN + q0) * LEN + tj * 128;
            #pragma unroll
            for (int ni = 0; ni < 8; ni++) {
                int c = wc * 64 + ni * 8 + 2 * t;
                int j = tj * 128 + c;
                int rp = j - q0 + (MRP - 1);
                float r0 = (rp >= 0 && rp < MRP) ? Rrow[rp] : 0.f;
                int rp1 = rp + 1;
                float r1 = (rp1 >= 0 && rp1 < MRP) ? Rrow[rp1] : 0.f;
                float x0 = acc[mi][ni][2 * rh + 0] + r0;
                float x1 = acc[mi][ni][2 * rh + 1] + r1;
                *(float2*)(Wrow + c) = make_float2(x0, x1);
            }
        }
    }
}

// ---------------- row softmax ----------------------------------------------
__global__ void __launch_bounds__(256) k_softmax(float* __restrict__ Wt) {
    const int q  = blockIdx.x & (LEN - 1);
    const int bh = blockIdx.x >> 11;
    float* Wrow = Wt + ((size_t)bh * LEN + q) * LEN;
    const int tid = threadIdx.x;
    const int ja = tid * 4, jb = 1024 + tid * 4;
    float4 wa = make_float4(-3e38f, -3e38f, -3e38f, -3e38f), wb = wa;
    if (ja <= q) wa = *(const float4*)(Wrow + ja);
    if (jb <= q) wb = *(const float4*)(Wrow + jb);
    float va[4] = {wa.x, wa.y, wa.z, wa.w};
    float vb[4] = {wb.x, wb.y, wb.z, wb.w};

    float m = -3.0e38f;
    #pragma unroll
    for (int c = 0; c < 4; c++) {
        if (ja + c <= q) m = fmaxf(m, va[c]);
        if (jb + c <= q) m = fmaxf(m, vb[c]);
    }
    __shared__ float red[9];
    #pragma unroll
    for (int o = 16; o > 0; o >>= 1) m = fmaxf(m, __shfl_xor_sync(0xffffffffu, m, o));
    if ((tid & 31) == 0) red[tid >> 5] = m;
    __syncthreads();
    if (tid == 0) {
        float x = red[0];
        #pragma unroll
        for (int w = 1; w < 8; w++) x = fmaxf(x, red[w]);
        red[8] = x;
    }
    __syncthreads();
    const float bm = red[8];

    float ea[4], eb[4], s = 0.f;
    #pragma unroll
    for (int c = 0; c < 4; c++) {
        ea[c] = (ja + c <= q) ? __expf(va[c] - bm) : 0.f;
        eb[c] = (jb + c <= q) ? __expf(vb[c] - bm) : 0.f;
        s += ea[c] + eb[c];
    }
    __syncthreads();
    #pragma unroll
    for (int o = 16; o > 0; o >>= 1) s += __shfl_xor_sync(0xffffffffu, s, o);
    if ((tid & 31) == 0) red[tid >> 5] = s;
    __syncthreads();
    if (tid == 0) {
        float x = red[0];
        #pragma unroll
        for (int w = 1; w < 8; w++) x += red[w];
        red[8] = x;
    }
    __syncthreads();
    const float inv = 1.0f / red[8];
    *(float4*)(Wrow + ja) = make_float4(ea[0]*inv, ea[1]*inv, ea[2]*inv, ea[3]*inv);
    *(float4*)(Wrow + jb) = make_float4(eb[0]*inv, eb[1]*inv, eb[2]*inv, eb[3]*inv);
}

// ---------------- O = W @ V (split-K, register acc, atomic epilogue) -------
__global__ void __launch_bounds__(256, 2) k_pv(const float* __restrict__ Wt,
                                               const float* __restrict__ V,
                                               float* __restrict__ O) {
    extern __shared__ uint16_t smp[];
    const int s = blockIdx.x, bh = blockIdx.y;
    int ti, tj0, tj1;
    if (s < 8) { ti = s; tj0 = 0; tj1 = ti + 1; }
    else {
        int k2 = s - 8; ti = 8 + (k2 >> 1);
        int cnt = ti + 1, first = (cnt + 1) >> 1;
        if (k2 & 1) { tj0 = first; tj1 = cnt; } else { tj0 = 0; tj1 = first; }
    }
    uint32_t* WH = (uint32_t*)(smp + PV_WH);
    uint32_t* WL = (uint32_t*)(smp + PV_WL);
    uint32_t* VH = (uint32_t*)(smp + PV_VH);
    uint32_t* VL = (uint32_t*)(smp + PV_VL);

    const int tid = threadIdx.x, w = tid >> 5, lane = tid & 31;
    const int wr = w >> 1, wc = w & 1, g = lane >> 2, t = lane & 3;

    float acc[2][4][4];
    #pragma unroll
    for (int a = 0; a < 2; a++)
        #pragma unroll
        for (int b = 0; b < 4; b++)
            #pragma unroll
            for (int c = 0; c < 4; c++) acc[a][b][c] = 0.f;

    for (int tj = tj0; tj < tj1; tj++) {
        const float* Wg = Wt + ((size_t)bh * LEN + ti * 128) * LEN + tj * 128;
        const float* Vg = V  + ((size_t)bh * LEN + tj * 128) * DIM;
        __syncthreads();
        #pragma unroll
        for (int it = 0; it < 16; it++) {       // W: 128x128 -> 4096 float4
            int idx = tid + it * 256;
            int row = idx >> 5;
            int c4  = (idx & 31) * 4;
            int so  = (row * STP + c4) >> 1;
            float4 vv = *(const float4*)(Wg + (size_t)row * LEN + c4);
            uint32_t h, l;
            split_pair(vv.x, vv.y, h, l); WH[so] = h;     WL[so] = l;
            split_pair(vv.z, vv.w, h, l); WH[so + 1] = h; WL[so + 1] = l;
        }
        #pragma unroll
        for (int it = 0; it < 16; it++) {       // V^T: 64 d x 128 j pairs
            int idx = tid + it * 256;           // 4096 pairs
            int d  = idx & 63;
            int j0 = (idx >> 6) * 2;
            float x = Vg[(size_t)j0 * DIM + d];
            float y = Vg[(size_t)(j0 + 1) * DIM + d];
            uint32_t h, l;
            split_pair(x, y, h, l);
            int so = (d * STP + j0) >> 1;
            VH[so] = h; VL[so] = l;
        }
        __syncthreads();

        #pragma unroll
        for (int ks = 0; ks < 8; ks++) {
            const int k0 = ks * 16 + 2 * t;
            uint32_t ah[2][4], al[2][4];
            #pragma unroll
            for (int mi = 0; mi < 2; mi++) {
                int r = wr * 32 + mi * 16 + g;
                int o0 = (r * STP + k0) >> 1, o1 = ((r + 8) * STP + k0) >> 1;
                ah[mi][0] = WH[o0];     ah[mi][1] = WH[o1];
                ah[mi][2] = WH[o0 + 4]; ah[mi][3] = WH[o1 + 4];
                al[mi][0] = WL[o0];     al[mi][1] = WL[o1];
                al[mi][2] = WL[o0 + 4]; al[mi][3] = WL[o1 + 4];
            }
            #pragma unroll
            for (int ni = 0; ni < 4; ni++) {
                int n = wc * 32 + ni * 8 + g;
                int ob = (n * STP + k0) >> 1;
                uint32_t bh0 = VH[ob], bh1 = VH[ob + 4];
                uint32_t bl0 = VL[ob], bl1 = VL[ob + 4];
                #pragma unroll
                for (int mi = 0; mi < 2; mi++) {
                    mma16816(acc[mi][ni], ah[mi][0], ah[mi][1], ah[mi][2], ah[mi][3], bh0, bh1);
                    mma16816(acc[mi][ni], ah[mi][0], ah[mi][1], ah[mi][2], ah[mi][3], bl0, bl1);
                    mma16816(acc[mi][ni], al[mi][0], al[mi][1], al[mi][2], al[mi][3], bh0, bh1);
                }
            }
        }
    }

    #pragma unroll
    for (int mi = 0; mi < 2; mi++) {
        #pragma unroll
        for (int rh = 0; rh < 2; rh++) {
            int row = ti * 128 + wr * 32 + mi * 16 + g + rh * 8;
            float* orow = O + ((size_t)bh * LEN + row) * DIM;
            #pragma unroll
            for (int ni = 0; ni < 4; ni++) {
                int c = wc * 32 + ni * 8 + 2 * t;
                atomicAdd(orow + c,     acc[mi][ni][2 * rh + 0]);
                atomicAdd(orow + c + 1, acc[mi][ni][2 * rh + 1]);
            }
        }
    }
}

// ---------------------------------------------------------------------------
extern "C" void kernel_launch(void* const* d_in, const int* in_sizes, int n_in,
                              void* d_out, int out_size) {
    const float* q   = (const float*)d_in[0];
    const float* k   = (const float*)d_in[1];
    const float* v   = (const float*)d_in[2];
    const float* rel = (const float*)d_in[3];

    float* out = (float*)d_out;
    float* Wt  = out + OUT_ELEMS;

    cudaFuncSetAttribute(k_relgemm, cudaFuncAttributeMaxDynamicSharedMemorySize, QK_SMEM);
    cudaFuncSetAttribute(k_qk,      cudaFuncAttributeMaxDynamicSharedMemorySize, QK_SMEM);
    cudaFuncSetAttribute(k_pv,      cudaFuncAttributeMaxDynamicSharedMemorySize, PV_SMEM);

    k_zero<<<(unsigned)(OUT_ELEMS / 1024), 256>>>(out);

    dim3 g0(QT, MRP / 128, BHN);
    k_relgemm<<<g0, 256, QK_SMEM>>>(q, rel);

    dim3 g1(TRI, BHN);
    k_qk<<<g1, 256, QK_SMEM>>>(q, k, Wt);

    k_softmax<<<BHN * LEN, 256>>>(Wt);

    dim3 g2(24, BHN);
    k_pv<<<g2, 256, PV_SMEM>>>(Wt, v, out);
}